// round 9
// baseline (speedup 1.0000x reference)
#include <cuda_runtime.h>
#include <math.h>

#define L     4096
#define BATCH 16
#define CH    512     // H*E = 8*64
#define TOPK  24      // int(3.0 * ln(4096)) = 24
#define FPSCALE 1048576.0f   // 2^20 fixed point for deterministic accumulation
#define CPB   8       // channels per CTA in k_fft
#define PAD(i) ((i) + ((i) >> 4))
#define PBUF  4352    // PAD(4095)=4350 -> 4352 float2

// ---------------- scratch (device globals; no allocs) ----------------
__device__ float2    d_z[(size_t)BATCH * CH * L];   // packed z = q + i*k, (B,C,L)
__device__ long long d_S[BATCH * L * 2];            // per-b cross spectrum (f<=2048 used)
__device__ float2    d_tw[L];                       // e^{-2pi i m / L}
__device__ float     d_mean[BATCH * L];
__device__ int       d_idx[TOPK];
__device__ float     d_w[BATCH * TOPK];

// ---------------- complex helpers ----------------
__device__ __forceinline__ float2 cadd(float2 a, float2 b){ return make_float2(a.x+b.x, a.y+b.y); }
__device__ __forceinline__ float2 csub(float2 a, float2 b){ return make_float2(a.x-b.x, a.y-b.y); }
__device__ __forceinline__ float2 cmul(float2 a, float2 b){
    return make_float2(a.x*b.x - a.y*b.y, a.x*b.y + a.y*b.x);
}

// ---------------- K0a/K0b: twiddles + zero accumulators ----------------
__global__ void k_init_tw() {
    int i = blockIdx.x * blockDim.x + threadIdx.x;
    if (i < L) {
        double th = -2.0 * 3.14159265358979323846 * (double)i / (double)L;
        d_tw[i] = make_float2((float)cos(th), (float)sin(th));
    }
}
__global__ void k_init_S() {
    int i = blockIdx.x * blockDim.x + threadIdx.x;
    for (int j = i; j < BATCH * L * 2; j += gridDim.x * blockDim.x) d_S[j] = 0;
}

// ---------------- K1: transpose (B,L,C) -> (B,C,L), pack q+ik ----------------
__global__ void k_transpose(const float* __restrict__ q, const float* __restrict__ k) {
    __shared__ float2 tile[32][33];   // [t_local][c_local], padded
    int b  = blockIdx.z;
    int t0 = blockIdx.x * 32;
    int c0 = blockIdx.y * 32;
    int tx = threadIdx.x, ty = threadIdx.y;
    #pragma unroll
    for (int r = 0; r < 4; r++) {
        int t = t0 + ty + r * 8;
        size_t idx = ((size_t)b * L + t) * CH + c0 + tx;   // coalesced over c
        tile[ty + r * 8][tx] = make_float2(q[idx], k[idx]);
    }
    __syncthreads();
    #pragma unroll
    for (int r = 0; r < 4; r++) {
        int c = c0 + ty + r * 8;
        d_z[((size_t)b * CH + c) * L + t0 + tx] = tile[tx][ty + r * 8];  // coalesced over t
    }
}

// ---------------- register-resident 16-point DFT (natural order in/out) --------
__device__ __forceinline__ void dft16(float2* a) {
    const float2 W16[10] = {
        { 1.0f, 0.0f},
        { 0.9238795325f,-0.3826834324f},
        { 0.7071067812f,-0.7071067812f},
        { 0.3826834324f,-0.9238795325f},
        { 0.0f,-1.0f},
        {-0.3826834324f,-0.9238795325f},
        {-0.7071067812f,-0.7071067812f},
        {-0.9238795325f,-0.3826834324f},
        {-1.0f, 0.0f},
        {-0.9238795325f, 0.3826834324f}
    };
    float2 bb[4][4];
    #pragma unroll
    for (int n1 = 0; n1 < 4; n1++) {
        float2 x0 = a[n1], x1 = a[n1+4], x2 = a[n1+8], x3 = a[n1+12];
        float2 apc = cadd(x0,x2), amc = csub(x0,x2);
        float2 bpd = cadd(x1,x3), bmd = csub(x1,x3);
        float2 mjb = make_float2(bmd.y, -bmd.x);   // -i*(x1-x3)
        bb[n1][0] = cadd(apc,bpd);
        bb[n1][1] = cadd(amc,mjb);
        bb[n1][2] = csub(apc,bpd);
        bb[n1][3] = csub(amc,mjb);
    }
    #pragma unroll
    for (int k1 = 0; k1 < 4; k1++) {
        float2 y0 = bb[0][k1];
        float2 y1 = cmul(bb[1][k1], W16[k1]);
        float2 y2 = cmul(bb[2][k1], W16[2*k1]);
        float2 y3 = cmul(bb[3][k1], W16[3*k1]);
        float2 apc = cadd(y0,y2), amc = csub(y0,y2);
        float2 bpd = cadd(y1,y3), bmd = csub(y1,y3);
        float2 mjb = make_float2(bmd.y, -bmd.x);
        a[k1]      = cadd(apc,bpd);
        a[k1+4]    = cadd(amc,mjb);
        a[k1+8]    = csub(apc,bpd);
        a[k1+12]   = csub(amc,mjb);
    }
}

// Stockham stage store: out[u + 15*ps + s*jj] = tw4096[jj*ps] * r[jj]
__device__ __forceinline__ void stage_store(const float2* r, float2* buf, int u, int s) {
    int ps = (u / s) * s;
    float2 P[4], A[4];
    P[0] = make_float2(1.f, 0.f);
    P[1] = d_tw[ps];
    P[2] = cmul(P[1], P[1]);
    P[3] = cmul(P[2], P[1]);
    A[0] = make_float2(1.f, 0.f);
    A[1] = d_tw[4  * ps];
    A[2] = d_tw[8  * ps];
    A[3] = d_tw[12 * ps];
    int base = u + 15 * ps;
    #pragma unroll
    for (int jj = 0; jj < 16; jj++) {
        float2 w = cmul(A[jj >> 2], P[jj & 3]);
        buf[PAD(base + s * jj)] = cmul(w, r[jj]);
    }
}

// ---------------- K2: pipelined FFT + half-spectrum accumulate ----------------
__global__ void __launch_bounds__(256, 3) k_fft() {
    extern __shared__ float2 sm[];
    float2* bufA = sm;
    float2* bufB = sm + PBUF;
    int tid = threadIdx.x;
    int blk = blockIdx.x;            // 1024 blocks = 16 b * 64 groups
    int b   = blk >> 6;
    int c0  = (blk & 63) * CPB;

    float accx[8], accy[8], accN = 0.f;
    #pragma unroll
    for (int j = 0; j < 8; j++) { accx[j] = 0.f; accy[j] = 0.f; }

    const float2* zbase = d_z + ((size_t)(b * CH + c0)) * L;
    float2 r[16];
    // prologue: load channel 0
    #pragma unroll
    for (int j = 0; j < 16; j++) r[j] = zbase[tid + 256 * j];

    for (int cc = 0; cc < CPB; cc++) {
        float2* X = (cc & 1) ? bufB : bufA;   // stage0/stage2 buffer (parity ping-pong)
        float2* Y = (cc & 1) ? bufA : bufB;
        // stage 0 (s=1): r (preloaded) -> X
        dft16(r);
        stage_store(r, X, tid, 1);
        __syncthreads();
        // stage 1 (s=16): X -> Y
        #pragma unroll
        for (int j = 0; j < 16; j++) r[j] = X[PAD(tid + 256 * j)];
        dft16(r);
        stage_store(r, Y, tid, 16);
        __syncthreads();
        // stage 2 (s=256, twiddles=1): Y -> X
        #pragma unroll
        for (int j = 0; j < 16; j++) r[j] = Y[PAD(tid + 256 * j)];
        dft16(r);
        #pragma unroll
        for (int jj = 0; jj < 16; jj++) X[PAD(tid + 256 * jj)] = r[jj];
        __syncthreads();
        // prefetch next channel into r (regs are dead now; hides DRAM latency)
        if (cc + 1 < CPB) {
            const float2* zr = zbase + ((size_t)(cc + 1)) * L;
            #pragma unroll
            for (int j = 0; j < 16; j++) r[j] = zr[tid + 256 * j];
        }
        // unpack z=q+ik for f in [0,2048]; S[N-f]=conj(S[f]) by Hermitian symmetry
        #pragma unroll
        for (int j = 0; j < 8; j++) {
            int i = tid + 256 * j;                 // 0..2047
            float2 Zf = X[PAD(i)];
            float2 Zr = X[PAD((L - i) & (L - 1))];
            float qx = 0.5f * (Zf.x + Zr.x), qy =  0.5f * (Zf.y - Zr.y);
            float kx = 0.5f * (Zf.y + Zr.y), ky = -0.5f * (Zf.x - Zr.x);
            accx[j] += qx * kx + qy * ky;
            accy[j] += qy * kx - qx * ky;
        }
        if (tid == 0) {                            // Nyquist f=2048
            float2 Zn = X[PAD(2048)];
            accN += Zn.x * Zn.y;
        }
        // no trailing sync: next stage0 writes the OTHER buffer; its post-store
        // sync orders stage1's X-write after every warp's unpack X-reads.
    }

    long long* Sb = d_S + b * L * 2;
    #pragma unroll
    for (int j = 0; j < 8; j++) {
        int i = tid + 256 * j;
        atomicAdd((unsigned long long*)&Sb[2 * i],
                  (unsigned long long)(long long)llrintf(accx[j] * FPSCALE));
        atomicAdd((unsigned long long*)&Sb[2 * i + 1],
                  (unsigned long long)(long long)llrintf(accy[j] * FPSCALE));
    }
    if (tid == 0)
        atomicAdd((unsigned long long*)&Sb[2 * 2048],
                  (unsigned long long)(long long)llrintf(accN * FPSCALE));
}

// ---------------- radix-4 Stockham FFT (for K3; 16 CTAs, negligible) ------
__device__ __forceinline__ void fft4096_r4(float2* x0, float2* y0,
                                           const float2* __restrict__ tw, int tid) {
    float2* x = x0;
    float2* y = y0;
    #pragma unroll
    for (int stage = 0; stage < 6; stage++) {
        int s = 1 << (2 * stage);
        #pragma unroll
        for (int uu = 0; uu < 4; uu++) {
            int u  = tid + uu * 256;
            int ps = u & ~(s - 1);
            float2 a = x[u];
            float2 b = x[u + 1024];
            float2 c = x[u + 2048];
            float2 d = x[u + 3072];
            float2 apc = cadd(a, c), amc = csub(a, c);
            float2 bpd = cadd(b, d), bmd = csub(b, d);
            float2 jbmd = make_float2(-bmd.y, bmd.x);
            float2 w1 = tw[ps], w2 = tw[2 * ps], w3 = tw[3 * ps];
            int o = u + 3 * ps;
            y[o]         = cadd(apc, bpd);
            y[o + s]     = cmul(w1, csub(amc, jbmd));
            y[o + 2 * s] = cmul(w2, csub(apc, bpd));
            y[o + 3 * s] = cmul(w3, cadd(amc, jbmd));
        }
        __syncthreads();
        float2* t = x; x = y; y = t;
    }
}

// ---------------- K3: inverse transform -> mean_value ----------------
__global__ void k_irfft() {
    extern __shared__ float2 sm[];
    float2* A   = sm;
    float2* B   = sm + L;
    float2* tws = sm + 2 * L;
    int tid = threadIdx.x;
    int b   = blockIdx.x;
    const long long* Sb = d_S + b * L * 2;
    const float c1 = 1.0f / FPSCALE;
    for (int i = tid; i < L; i += 256) {
        int m = (i <= 2048) ? i : (L - i);       // stored half-spectrum index
        float sx = (float)Sb[2 * m]     * c1;
        float sy = (float)Sb[2 * m + 1] * c1;
        float sgn = (i <= 2048) ? -1.f : 1.f;    // feed A = conj(S[i])
        A[i] = make_float2(sx, sgn * sy);
        tws[i] = d_tw[i];
    }
    __syncthreads();
    fft4096_r4(A, B, tws, tid);
    const float c2 = 1.0f / ((float)L * (float)CH);
    for (int i = tid; i < L; i += 256) d_mean[b * L + i] = A[i].x * c2;
}

// ---------------- K4: top-k over batch-mean + per-batch softmax ----------------
__global__ void k_topk() {
    __shared__ float cm[L];
    __shared__ float rv[256];
    __shared__ int   ri[256];
    __shared__ int   sidx[TOPK];
    int tid = threadIdx.x;
    for (int i = tid; i < L; i += 256) {
        float s = 0.0f;
        #pragma unroll
        for (int b = 0; b < BATCH; b++) s += d_mean[b * L + i];
        cm[i] = s;
    }
    __syncthreads();
    for (int it = 0; it < TOPK; it++) {
        float best = -1e30f; int bi = 0;
        for (int i = tid; i < L; i += 256) {
            float vv = cm[i];
            if (vv > best) { best = vv; bi = i; }
        }
        rv[tid] = best; ri[tid] = bi;
        __syncthreads();
        for (int off = 128; off > 0; off >>= 1) {
            if (tid < off) {
                if (rv[tid + off] > rv[tid] ||
                    (rv[tid + off] == rv[tid] && ri[tid + off] < ri[tid])) {
                    rv[tid] = rv[tid + off]; ri[tid] = ri[tid + off];
                }
            }
            __syncthreads();
        }
        if (tid == 0) { sidx[it] = ri[0]; cm[ri[0]] = -1e30f; }
        __syncthreads();
    }
    if (tid < TOPK) d_idx[tid] = sidx[tid];
    if (tid < BATCH) {
        int b = tid;
        float vals[TOPK]; float mx = -1e30f;
        #pragma unroll
        for (int i = 0; i < TOPK; i++) { vals[i] = d_mean[b * L + sidx[i]]; mx = fmaxf(mx, vals[i]); }
        float ssum = 0.0f;
        #pragma unroll
        for (int i = 0; i < TOPK; i++) { vals[i] = expf(vals[i] - mx); ssum += vals[i]; }
        #pragma unroll
        for (int i = 0; i < TOPK; i++) d_w[b * TOPK + i] = vals[i] / ssum;
    }
}

// ---------------- K5: smem-resident weighted shifted aggregation ----------------
// CTA = (b, group of 4 channels). v slab for these channels (4096 x float4 = 64 KB)
// lives in DYNAMIC smem; the 24 shifted reads hit smem instead of L2.
__global__ void __launch_bounds__(256) k_agg2(const float4* __restrict__ v4,
                                              float4* __restrict__ o4) {
    extern __shared__ float4 dsm[];
    float4* sv  = dsm;                         // [L] = 64 KB
    int*    ssi = (int*)(dsm + L);             // [TOPK]
    float*  ssw = (float*)(ssi + TOPK);        // [TOPK]
    int tid = threadIdx.x;
    int b   = blockIdx.x >> 7;           // 2048 blocks = 16 b * 128 groups
    int g   = blockIdx.x & 127;          // channel group (4 floats)
    const float4* vb = v4 + (size_t)b * L * 128 + g;   // row stride 128 float4
    for (int m = tid; m < L; m += 256) sv[m] = vb[(size_t)m * 128];
    if (tid < TOPK) { ssi[tid] = d_idx[tid]; ssw[tid] = d_w[b * TOPK + tid]; }
    __syncthreads();

    float4* ob = o4 + (size_t)b * L * 128 + g;
    for (int jj = 0; jj < 16; jj += 4) {
        float4 acc[4];
        #pragma unroll
        for (int u = 0; u < 4; u++) acc[u] = make_float4(0.f, 0.f, 0.f, 0.f);
        #pragma unroll
        for (int i = 0; i < TOPK; i++) {
            int   s = ssi[i];
            float w = ssw[i];
            #pragma unroll
            for (int u = 0; u < 4; u++) {
                int t  = tid + 256 * (jj + u);
                int tt = (t + s) & (L - 1);
                float4 vv = sv[tt];
                acc[u].x += w * vv.x; acc[u].y += w * vv.y;
                acc[u].z += w * vv.z; acc[u].w += w * vv.w;
            }
        }
        #pragma unroll
        for (int u = 0; u < 4; u++)
            ob[(size_t)(tid + 256 * (jj + u)) * 128] = acc[u];
    }
}

// ---------------- launcher ----------------
extern "C" void kernel_launch(void* const* d_in, const int* in_sizes, int n_in,
                              void* d_out, int out_size) {
    const float* q = (const float*)d_in[0];
    const float* k = (const float*)d_in[1];
    const float* v = (const float*)d_in[2];

    const int smem_fft  = 2 * PBUF * sizeof(float2);               // 69,632 B
    const int smem_ifft = 3 * L * sizeof(float2);                  // 96 KB
    const int smem_agg  = L * sizeof(float4) + TOPK * 8;           // 65,728 B
    cudaFuncSetAttribute(k_fft,   cudaFuncAttributeMaxDynamicSharedMemorySize, smem_fft);
    cudaFuncSetAttribute(k_irfft, cudaFuncAttributeMaxDynamicSharedMemorySize, smem_ifft);
    cudaFuncSetAttribute(k_agg2,  cudaFuncAttributeMaxDynamicSharedMemorySize, smem_agg);

    k_init_tw<<<16, 256>>>();                                            // launch 1
    k_init_S<<<32, 256>>>();                                             // launch 2
    k_transpose<<<dim3(L / 32, CH / 32, BATCH), dim3(32, 8, 1)>>>(q, k); // launch 3
    k_fft<<<(BATCH * CH) / CPB, 256, smem_fft>>>();                      // launch 4 (ncu slot)
    k_irfft<<<BATCH, 256, smem_ifft>>>();
    k_topk<<<1, 256>>>();
    k_agg2<<<BATCH * 128, 256, smem_agg>>>((const float4*)v, (float4*)d_out);
}

// round 11
// speedup vs baseline: 1.0761x; 1.0761x over previous
#include <cuda_runtime.h>
#include <math.h>

#define L     4096
#define BATCH 16
#define CH    512     // H*E = 8*64
#define TOPK  24      // int(3.0 * ln(4096)) = 24
#define FPSCALE 1048576.0f   // 2^20 fixed point for deterministic accumulation
#define CPB   8       // channels per CTA in k_fft
#define PAD(i) ((i) + ((i) >> 4))
#define PBUF  4352    // PAD(4095)=4350 -> 4352 float2

// ---------------- scratch (device globals; no allocs) ----------------
__device__ float2    d_z[(size_t)BATCH * CH * L];   // packed z = q + i*k, (B,C,L)
__device__ long long d_S[BATCH * L * 2];            // per-b cross spectrum (f<=2048 used)
__device__ float2    d_tw[L];                       // e^{-2pi i m / L}
__device__ float     d_mean[BATCH * L];
__device__ int       d_idx[TOPK];
__device__ float     d_w[BATCH * TOPK];

// ---------------- complex helpers ----------------
__device__ __forceinline__ float2 cadd(float2 a, float2 b){ return make_float2(a.x+b.x, a.y+b.y); }
__device__ __forceinline__ float2 csub(float2 a, float2 b){ return make_float2(a.x-b.x, a.y-b.y); }
__device__ __forceinline__ float2 cmul(float2 a, float2 b){
    return make_float2(a.x*b.x - a.y*b.y, a.x*b.y + a.y*b.x);
}

// ---------------- K0a/K0b: twiddles + zero accumulators ----------------
__global__ void k_init_tw() {
    int i = blockIdx.x * blockDim.x + threadIdx.x;
    if (i < L) {
        double th = -2.0 * 3.14159265358979323846 * (double)i / (double)L;
        d_tw[i] = make_float2((float)cos(th), (float)sin(th));
    }
}
__global__ void k_init_S() {
    int i = blockIdx.x * blockDim.x + threadIdx.x;
    for (int j = i; j < BATCH * L * 2; j += gridDim.x * blockDim.x) d_S[j] = 0;
}

// ---------------- K1: transpose (B,L,C) -> (B,C,L), pack q+ik ----------------
__global__ void k_transpose(const float* __restrict__ q, const float* __restrict__ k) {
    __shared__ float2 tile[32][33];   // [t_local][c_local], padded
    int b  = blockIdx.z;
    int t0 = blockIdx.x * 32;
    int c0 = blockIdx.y * 32;
    int tx = threadIdx.x, ty = threadIdx.y;
    #pragma unroll
    for (int r = 0; r < 4; r++) {
        int t = t0 + ty + r * 8;
        size_t idx = ((size_t)b * L + t) * CH + c0 + tx;   // coalesced over c
        tile[ty + r * 8][tx] = make_float2(q[idx], k[idx]);
    }
    __syncthreads();
    #pragma unroll
    for (int r = 0; r < 4; r++) {
        int c = c0 + ty + r * 8;
        d_z[((size_t)b * CH + c) * L + t0 + tx] = tile[tx][ty + r * 8];  // coalesced over t
    }
}

// ---------------- register-resident 16-point DFT (natural order in/out) --------
__device__ __forceinline__ void dft16(float2* a) {
    const float2 W16[10] = {
        { 1.0f, 0.0f},
        { 0.9238795325f,-0.3826834324f},
        { 0.7071067812f,-0.7071067812f},
        { 0.3826834324f,-0.9238795325f},
        { 0.0f,-1.0f},
        {-0.3826834324f,-0.9238795325f},
        {-0.7071067812f,-0.7071067812f},
        {-0.9238795325f,-0.3826834324f},
        {-1.0f, 0.0f},
        {-0.9238795325f, 0.3826834324f}
    };
    float2 bb[4][4];
    #pragma unroll
    for (int n1 = 0; n1 < 4; n1++) {
        float2 x0 = a[n1], x1 = a[n1+4], x2 = a[n1+8], x3 = a[n1+12];
        float2 apc = cadd(x0,x2), amc = csub(x0,x2);
        float2 bpd = cadd(x1,x3), bmd = csub(x1,x3);
        float2 mjb = make_float2(bmd.y, -bmd.x);   // -i*(x1-x3)
        bb[n1][0] = cadd(apc,bpd);
        bb[n1][1] = cadd(amc,mjb);
        bb[n1][2] = csub(apc,bpd);
        bb[n1][3] = csub(amc,mjb);
    }
    #pragma unroll
    for (int k1 = 0; k1 < 4; k1++) {
        float2 y0 = bb[0][k1];
        float2 y1 = cmul(bb[1][k1], W16[k1]);
        float2 y2 = cmul(bb[2][k1], W16[2*k1]);
        float2 y3 = cmul(bb[3][k1], W16[3*k1]);
        float2 apc = cadd(y0,y2), amc = csub(y0,y2);
        float2 bpd = cadd(y1,y3), bmd = csub(y1,y3);
        float2 mjb = make_float2(bmd.y, -bmd.x);
        a[k1]      = cadd(apc,bpd);
        a[k1+4]    = cadd(amc,mjb);
        a[k1+8]    = csub(apc,bpd);
        a[k1+12]   = csub(amc,mjb);
    }
}

// Stockham stage store: out[u + 15*ps + s*jj] = tw4096[jj*ps] * r[jj]
__device__ __forceinline__ void stage_store(const float2* r, float2* buf, int u, int s) {
    int ps = (u / s) * s;
    float2 P[4], A[4];
    P[0] = make_float2(1.f, 0.f);
    P[1] = d_tw[ps];
    P[2] = cmul(P[1], P[1]);
    P[3] = cmul(P[2], P[1]);
    A[0] = make_float2(1.f, 0.f);
    A[1] = d_tw[4  * ps];
    A[2] = d_tw[8  * ps];
    A[3] = d_tw[12 * ps];
    int base = u + 15 * ps;
    #pragma unroll
    for (int jj = 0; jj < 16; jj++) {
        float2 w = cmul(A[jj >> 2], P[jj & 3]);
        buf[PAD(base + s * jj)] = cmul(w, r[jj]);
    }
}

// ---------------- K2: pipelined FFT + half-spectrum accumulate ----------------
__global__ void __launch_bounds__(256, 3) k_fft() {
    extern __shared__ float2 sm[];
    float2* bufA = sm;
    float2* bufB = sm + PBUF;
    int tid = threadIdx.x;
    int blk = blockIdx.x;            // 1024 blocks = 16 b * 64 groups
    int b   = blk >> 6;
    int c0  = (blk & 63) * CPB;

    float accx[8], accy[8], accN = 0.f;
    #pragma unroll
    for (int j = 0; j < 8; j++) { accx[j] = 0.f; accy[j] = 0.f; }

    const float2* zbase = d_z + ((size_t)(b * CH + c0)) * L;
    float2 r[16];
    // prologue: load channel 0
    #pragma unroll
    for (int j = 0; j < 16; j++) r[j] = zbase[tid + 256 * j];

    for (int cc = 0; cc < CPB; cc++) {
        float2* X = (cc & 1) ? bufB : bufA;   // stage0/stage2 buffer (parity ping-pong)
        float2* Y = (cc & 1) ? bufA : bufB;
        // stage 0 (s=1): r (preloaded) -> X
        dft16(r);
        stage_store(r, X, tid, 1);
        __syncthreads();
        // stage 1 (s=16): X -> Y
        #pragma unroll
        for (int j = 0; j < 16; j++) r[j] = X[PAD(tid + 256 * j)];
        dft16(r);
        stage_store(r, Y, tid, 16);
        __syncthreads();
        // stage 2 (s=256, twiddles=1): Y -> X
        #pragma unroll
        for (int j = 0; j < 16; j++) r[j] = Y[PAD(tid + 256 * j)];
        dft16(r);
        #pragma unroll
        for (int jj = 0; jj < 16; jj++) X[PAD(tid + 256 * jj)] = r[jj];
        __syncthreads();
        // prefetch next channel into r (regs are dead now; hides DRAM latency)
        if (cc + 1 < CPB) {
            const float2* zr = zbase + ((size_t)(cc + 1)) * L;
            #pragma unroll
            for (int j = 0; j < 16; j++) r[j] = zr[tid + 256 * j];
        }
        // unpack z=q+ik for f in [0,2048]; S[N-f]=conj(S[f]) by Hermitian symmetry
        #pragma unroll
        for (int j = 0; j < 8; j++) {
            int i = tid + 256 * j;                 // 0..2047
            float2 Zf = X[PAD(i)];
            float2 Zr = X[PAD((L - i) & (L - 1))];
            float qx = 0.5f * (Zf.x + Zr.x), qy =  0.5f * (Zf.y - Zr.y);
            float kx = 0.5f * (Zf.y + Zr.y), ky = -0.5f * (Zf.x - Zr.x);
            accx[j] += qx * kx + qy * ky;
            accy[j] += qy * kx - qx * ky;
        }
        if (tid == 0) {                            // Nyquist f=2048
            float2 Zn = X[PAD(2048)];
            accN += Zn.x * Zn.y;
        }
        // no trailing sync: next stage0 writes the OTHER buffer; its post-store
        // sync orders stage1's X-write after every warp's unpack X-reads.
    }

    long long* Sb = d_S + b * L * 2;
    #pragma unroll
    for (int j = 0; j < 8; j++) {
        int i = tid + 256 * j;
        atomicAdd((unsigned long long*)&Sb[2 * i],
                  (unsigned long long)(long long)llrintf(accx[j] * FPSCALE));
        atomicAdd((unsigned long long*)&Sb[2 * i + 1],
                  (unsigned long long)(long long)llrintf(accy[j] * FPSCALE));
    }
    if (tid == 0)
        atomicAdd((unsigned long long*)&Sb[2 * 2048],
                  (unsigned long long)(long long)llrintf(accN * FPSCALE));
}

// ---------------- radix-4 Stockham FFT (for K3; 16 CTAs, negligible) ------
__device__ __forceinline__ void fft4096_r4(float2* x0, float2* y0,
                                           const float2* __restrict__ tw, int tid) {
    float2* x = x0;
    float2* y = y0;
    #pragma unroll
    for (int stage = 0; stage < 6; stage++) {
        int s = 1 << (2 * stage);
        #pragma unroll
        for (int uu = 0; uu < 4; uu++) {
            int u  = tid + uu * 256;
            int ps = u & ~(s - 1);
            float2 a = x[u];
            float2 b = x[u + 1024];
            float2 c = x[u + 2048];
            float2 d = x[u + 3072];
            float2 apc = cadd(a, c), amc = csub(a, c);
            float2 bpd = cadd(b, d), bmd = csub(b, d);
            float2 jbmd = make_float2(-bmd.y, bmd.x);
            float2 w1 = tw[ps], w2 = tw[2 * ps], w3 = tw[3 * ps];
            int o = u + 3 * ps;
            y[o]         = cadd(apc, bpd);
            y[o + s]     = cmul(w1, csub(amc, jbmd));
            y[o + 2 * s] = cmul(w2, csub(apc, bpd));
            y[o + 3 * s] = cmul(w3, cadd(amc, jbmd));
        }
        __syncthreads();
        float2* t = x; x = y; y = t;
    }
}

// ---------------- K3: inverse transform -> mean_value ----------------
__global__ void k_irfft() {
    extern __shared__ float2 sm[];
    float2* A   = sm;
    float2* B   = sm + L;
    float2* tws = sm + 2 * L;
    int tid = threadIdx.x;
    int b   = blockIdx.x;
    const long long* Sb = d_S + b * L * 2;
    const float c1 = 1.0f / FPSCALE;
    for (int i = tid; i < L; i += 256) {
        int m = (i <= 2048) ? i : (L - i);       // stored half-spectrum index
        float sx = (float)Sb[2 * m]     * c1;
        float sy = (float)Sb[2 * m + 1] * c1;
        float sgn = (i <= 2048) ? -1.f : 1.f;    // feed A = conj(S[i])
        A[i] = make_float2(sx, sgn * sy);
        tws[i] = d_tw[i];
    }
    __syncthreads();
    fft4096_r4(A, B, tws, tid);
    const float c2 = 1.0f / ((float)L * (float)CH);
    for (int i = tid; i < L; i += 256) d_mean[b * L + i] = A[i].x * c2;
}

// ---------------- K4: top-k over batch-mean + per-batch softmax ----------------
__global__ void k_topk() {
    __shared__ float cm[L];
    __shared__ float rv[256];
    __shared__ int   ri[256];
    __shared__ int   sidx[TOPK];
    int tid = threadIdx.x;
    for (int i = tid; i < L; i += 256) {
        float s = 0.0f;
        #pragma unroll
        for (int b = 0; b < BATCH; b++) s += d_mean[b * L + i];
        cm[i] = s;
    }
    __syncthreads();
    for (int it = 0; it < TOPK; it++) {
        float best = -1e30f; int bi = 0;
        for (int i = tid; i < L; i += 256) {
            float vv = cm[i];
            if (vv > best) { best = vv; bi = i; }
        }
        rv[tid] = best; ri[tid] = bi;
        __syncthreads();
        for (int off = 128; off > 0; off >>= 1) {
            if (tid < off) {
                if (rv[tid + off] > rv[tid] ||
                    (rv[tid + off] == rv[tid] && ri[tid + off] < ri[tid])) {
                    rv[tid] = rv[tid + off]; ri[tid] = ri[tid + off];
                }
            }
            __syncthreads();
        }
        if (tid == 0) { sidx[it] = ri[0]; cm[ri[0]] = -1e30f; }
        __syncthreads();
    }
    if (tid < TOPK) d_idx[tid] = sidx[tid];
    if (tid < BATCH) {
        int b = tid;
        float vals[TOPK]; float mx = -1e30f;
        #pragma unroll
        for (int i = 0; i < TOPK; i++) { vals[i] = d_mean[b * L + sidx[i]]; mx = fmaxf(mx, vals[i]); }
        float ssum = 0.0f;
        #pragma unroll
        for (int i = 0; i < TOPK; i++) { vals[i] = expf(vals[i] - mx); ssum += vals[i]; }
        #pragma unroll
        for (int i = 0; i < TOPK; i++) d_w[b * TOPK + i] = vals[i] / ssum;
    }
}

// ---------------- K5: weighted shifted aggregation (coalesced L2 streaming) ----
__global__ void k_agg(const float4* __restrict__ v4, float4* __restrict__ o4) {
    __shared__ int   si[TOPK];
    __shared__ float sw[TOPK];
    int t = blockIdx.x, b = blockIdx.y, tid = threadIdx.x;   // 128 threads, float4 over 512 ch
    if (tid < TOPK) { si[tid] = d_idx[tid]; sw[tid] = d_w[b * TOPK + tid]; }
    __syncthreads();
    const float4* vb = v4 + (size_t)b * L * 128;
    float4 acc = make_float4(0.f, 0.f, 0.f, 0.f);
    #pragma unroll
    for (int i = 0; i < TOPK; i++) {
        int tt = (t + si[i]) & (L - 1);
        float4 vv = vb[tt * 128 + tid];
        float w = sw[i];
        acc.x += w * vv.x; acc.y += w * vv.y; acc.z += w * vv.z; acc.w += w * vv.w;
    }
    o4[((size_t)b * L + t) * 128 + tid] = acc;
}

// ---------------- launcher ----------------
extern "C" void kernel_launch(void* const* d_in, const int* in_sizes, int n_in,
                              void* d_out, int out_size) {
    const float* q = (const float*)d_in[0];
    const float* k = (const float*)d_in[1];
    const float* v = (const float*)d_in[2];

    const int smem_fft  = 2 * PBUF * sizeof(float2);   // 69,632 B
    const int smem_ifft = 3 * L * sizeof(float2);      // 96 KB
    cudaFuncSetAttribute(k_fft,   cudaFuncAttributeMaxDynamicSharedMemorySize, smem_fft);
    cudaFuncSetAttribute(k_irfft, cudaFuncAttributeMaxDynamicSharedMemorySize, smem_ifft);

    k_init_tw<<<16, 256>>>();                                            // launch 1
    k_init_S<<<32, 256>>>();                                             // launch 2
    k_transpose<<<dim3(L / 32, CH / 32, BATCH), dim3(32, 8, 1)>>>(q, k); // launch 3
    k_fft<<<(BATCH * CH) / CPB, 256, smem_fft>>>();                      // launch 4 (ncu slot)
    k_irfft<<<BATCH, 256, smem_ifft>>>();
    k_topk<<<1, 256>>>();
    k_agg<<<dim3(L, BATCH), 128>>>((const float4*)v, (float4*)d_out);
}